// round 15
// baseline (speedup 1.0000x reference)
#include <cuda_runtime.h>
#include <cstdint>

#define BATCH   65536
#define LATENT  128
#define HID     256
#define GATES   1024
#define SEQN    50
#define NUCV    4
#define VOCAB   5
#define SOS_TOK 4

#define TB       32            // rows per CTA
#define CH       16            // rows per accumulation sweep
#define NTHREADS 256
#define PAD      36            // hT row stride: 144B = 16B-aligned for LDS.128

// SMEM layout (float offsets)
#define OFF_HA    0
#define OFF_HB    9216         // 256*PAD
#define OFF_ZS    9216         // zsm aliases hbuf1 (prologue-only use)
#define OFF_E     18432
#define OFF_WOUT  23552
#define OFF_BOUT  24576
#define OFF_TOK   24580
#define SMEM_FLOATS 24612
#define SMEM_BYTES  (SMEM_FLOATS * 4)   // 98448 B -> 2 CTAs/SM

struct StepKeys { unsigned int k0[SEQN]; unsigned int k1[SEQN]; };

__device__ float g_E[VOCAB * GATES];            // emb[v]@W_ih + b_ih (folded)
// duplicated-packed W_hh: [k][j] = (wi,wi,wf,wf,wg,wg,wo,wo); +1 k-row of zeros
__device__ float g_W2f[(size_t)(HID + 1) * HID * 8];
// precomputed exact gumbel noise, layout [s][b][n]
__device__ float g_gum[(size_t)SEQN * BATCH * NUCV];

// ---------------- packed f32x2 helpers (Blackwell sm_103a) ----------------
__device__ __forceinline__ void unpack2(unsigned long long v, float& lo, float& hi) {
    asm("mov.b64 {%0, %1}, %2;" : "=f"(lo), "=f"(hi) : "l"(v));
}
// per-lane IEEE RN fused multiply-add on packed 2xf32 — bit-identical to
// two scalar __fmaf_rn per lane
__device__ __forceinline__ unsigned long long fma2(unsigned long long a,
                                                   unsigned long long b,
                                                   unsigned long long c) {
    unsigned long long d;
    asm("fma.rn.f32x2 %0, %1, %2, %3;" : "=l"(d) : "l"(a), "l"(b), "l"(c));
    return d;
}

// ---------------- Threefry-2x32 (matches jax/_src/prng.py) ----------------
__host__ __device__ __forceinline__ unsigned int rotl32(unsigned int x, int d) {
    return (x << d) | (x >> (32 - d));
}

__host__ __device__ __forceinline__ void tf2x32(unsigned int k0, unsigned int k1,
                                                unsigned int x0, unsigned int x1,
                                                unsigned int& o0, unsigned int& o1)
{
    unsigned int k2 = k0 ^ k1 ^ 0x1BD11BDAu;
    x0 += k0; x1 += k1;
    x0 += x1; x1 = rotl32(x1, 13); x1 ^= x0;
    x0 += x1; x1 = rotl32(x1, 15); x1 ^= x0;
    x0 += x1; x1 = rotl32(x1, 26); x1 ^= x0;
    x0 += x1; x1 = rotl32(x1, 6);  x1 ^= x0;
    x0 += k1; x1 += k2 + 1u;
    x0 += x1; x1 = rotl32(x1, 17); x1 ^= x0;
    x0 += x1; x1 = rotl32(x1, 29); x1 ^= x0;
    x0 += x1; x1 = rotl32(x1, 16); x1 ^= x0;
    x0 += x1; x1 = rotl32(x1, 24); x1 ^= x0;
    x0 += k2; x1 += k0 + 2u;
    x0 += x1; x1 = rotl32(x1, 13); x1 ^= x0;
    x0 += x1; x1 = rotl32(x1, 15); x1 ^= x0;
    x0 += x1; x1 = rotl32(x1, 26); x1 ^= x0;
    x0 += x1; x1 = rotl32(x1, 6);  x1 ^= x0;
    x0 += k0; x1 += k1 + 3u;
    x0 += x1; x1 = rotl32(x1, 17); x1 ^= x0;
    x0 += x1; x1 = rotl32(x1, 29); x1 ^= x0;
    x0 += x1; x1 = rotl32(x1, 16); x1 ^= x0;
    x0 += x1; x1 = rotl32(x1, 24); x1 ^= x0;
    x0 += k1; x1 += k2 + 4u;
    x0 += x1; x1 = rotl32(x1, 13); x1 ^= x0;
    x0 += x1; x1 = rotl32(x1, 15); x1 ^= x0;
    x0 += x1; x1 = rotl32(x1, 26); x1 ^= x0;
    x0 += x1; x1 = rotl32(x1, 6);  x1 ^= x0;
    x0 += k2; x1 += k0 + 5u;
    o0 = x0; o1 = x1;
}

// ---------------- XLA-exact activations ----------------
__device__ __forceinline__ float xla_tanh(float x) {
    float ax = fabsf(x);
    float xc = fminf(fmaxf(x, -7.90531110763549805f), 7.90531110763549805f);
    float x2 = __fmul_rn(xc, xc);
    float p = -2.76076847742355e-16f;
    p = __fadd_rn(__fmul_rn(p, x2), 2.00018790482477e-13f);
    p = __fadd_rn(__fmul_rn(p, x2), -8.60467152213735e-11f);
    p = __fadd_rn(__fmul_rn(p, x2), 5.12229709037114e-08f);
    p = __fadd_rn(__fmul_rn(p, x2), 1.48572235717979e-05f);
    p = __fadd_rn(__fmul_rn(p, x2), 6.37261928875436e-04f);
    p = __fadd_rn(__fmul_rn(p, x2), 4.89352455891786e-03f);
    float num = __fmul_rn(xc, p);
    float q = 1.19825839466702e-06f;
    q = __fadd_rn(__fmul_rn(q, x2), 1.18534705686654e-04f);
    q = __fadd_rn(__fmul_rn(q, x2), 2.26843463243900e-03f);
    q = __fadd_rn(__fmul_rn(q, x2), 4.89352518554385e-03f);
    float r = __fdiv_rn(num, q);
    return (ax < 0.0004f) ? x : r;
}

__device__ __forceinline__ float xla_sigmoid(float x) {
    return __fadd_rn(0.5f, __fmul_rn(0.5f, xla_tanh(__fmul_rn(0.5f, x))));
}

// correctly-rounded f32 log via double
__device__ __forceinline__ float exact_logf(float x) {
    return (float)log((double)x);
}

// ---------------- E-table kernel: E[v][col] = emb[v]@W_ih[:,col] + b_ih[col] ----
// (b_ih folded with the exact same __fadd_rn the main kernel used to apply)
__global__ void ecomp_kernel(const float* __restrict__ emb,
                             const float* __restrict__ W_ih,
                             const float* __restrict__ b_ih) {
    int idx = blockIdx.x * blockDim.x + threadIdx.x;
    if (idx >= VOCAB * GATES) return;
    int v = idx / GATES, col = idx - v * GATES;
    float acc = 0.0f;
    for (int k = 0; k < HID; k++)
        acc = __fmaf_rn(emb[v * HID + k], W_ih[k * GATES + col], acc);
    g_E[idx] = __fadd_rn(acc, b_ih[col]);
}

// ---------------- W repack kernel: g_W2f[k][j] = dup-packed gate weights ----
__global__ void wpack_kernel(const float* __restrict__ W_hh) {
    int idx = blockIdx.x * blockDim.x + threadIdx.x;
    if (idx >= (HID + 1) * HID) return;
    int k = idx >> 8, j = idx & (HID - 1);
    float wi = 0.f, wf = 0.f, wg = 0.f, wo = 0.f;
    if (k < HID) {
        wi = W_hh[(size_t)k * GATES + j];
        wf = W_hh[(size_t)k * GATES + 256 + j];
        wg = W_hh[(size_t)k * GATES + 512 + j];
        wo = W_hh[(size_t)k * GATES + 768 + j];
    }
    float* d = g_W2f + (size_t)idx * 8;
    d[0] = wi; d[1] = wi; d[2] = wf; d[3] = wf;
    d[4] = wg; d[5] = wg; d[6] = wo; d[7] = wo;
}

// ---------------- Gumbel precompute: exact, data-independent ----------------
__global__ void gumbel_kernel(StepKeys keys) {
    size_t idx = (size_t)blockIdx.x * blockDim.x + threadIdx.x;
    if (idx >= (size_t)SEQN * BATCH * NUCV) return;
    int s = (int)(idx / ((size_t)BATCH * NUCV));
    unsigned rem = (unsigned)(idx - (size_t)s * BATCH * NUCV);   // b*4+n
    unsigned o0, o1;
    tf2x32(keys.k0[s], keys.k1[s], 0u, rem, o0, o1);
    unsigned bits = o0 ^ o1;
    unsigned fb = (bits >> 9) | 0x3f800000u;
    float u = __fadd_rn(__uint_as_float(fb), -1.0f);
    u = fmaxf(u, 1.17549435e-38f);              // minval = tiny
    float lu  = exact_logf(u);
    g_gum[idx] = -exact_logf(-lu);
}

// ---------------- Main persistent-per-CTA LSTM kernel ----------------
__global__ void __launch_bounds__(NTHREADS, 2)
rnn_main(const float* __restrict__ z,
         const float* __restrict__ W_lh, const float* __restrict__ b_lh,
         const float* __restrict__ W_lc, const float* __restrict__ b_lc,
         const float* __restrict__ b_hh,
         const float* __restrict__ W_out, const float* __restrict__ b_out,
         float* __restrict__ out)
{
    extern __shared__ float sm[];
    float* hbuf0   = sm + OFF_HA;      // hT[unit][row], PAD-strided
    float* hbuf1   = sm + OFF_HB;
    float* zsm     = sm + OFF_ZS;      // aliases hbuf1 (prologue only)
    float* Esm     = sm + OFF_E;       // [5][1024] (b_ih folded)
    float* WoutSm  = sm + OFF_WOUT;    // [256][4]
    float* boutSm  = sm + OFF_BOUT;    // [4]
    int*   tokSm   = (int*)(sm + OFF_TOK);  // [32]

    const int tid = threadIdx.x;
    const int j   = tid;                     // hidden unit owned by this thread
    const int rowBase = blockIdx.x * TB;

    // cooperative SMEM fills
    for (int i = tid; i < VOCAB * GATES; i += NTHREADS) Esm[i] = g_E[i];
    for (int i = tid; i < HID * NUCV; i += NTHREADS)    WoutSm[i] = W_out[i];
    if (tid < NUCV) boutSm[tid] = b_out[tid];
    if (tid < TB)   tokSm[tid]  = SOS_TOK;
    for (int i = tid; i < TB * LATENT; i += NTHREADS)
        zsm[i] = z[(size_t)rowBase * LATENT + i];
    __syncthreads();

    // per-thread persistent cell state c[row] for unit j
    float creg[TB];

    // ---- prologue: h0 = tanh(z@W_lh + b_lh), c0 = tanh(z@W_lc + b_lc) ----
    {
        const float* wlh = W_lh + j;
        const float* wlc = W_lc + j;
        float blh = b_lh[j], blc = b_lc[j];
        #pragma unroll
        for (int ch = 0; ch < TB / CH; ch++) {
            float ah[CH], ac[CH];
            #pragma unroll
            for (int rr = 0; rr < CH; rr++) { ah[rr] = 0.0f; ac[rr] = 0.0f; }
            for (int k = 0; k < LATENT; k++) {
                float wh = wlh[k * HID];
                float wc = wlc[k * HID];
                #pragma unroll
                for (int rr = 0; rr < CH; rr++) {
                    float zv = zsm[(ch * CH + rr) * LATENT + k];
                    ah[rr] = __fmaf_rn(zv, wh, ah[rr]);
                    ac[rr] = __fmaf_rn(zv, wc, ac[rr]);
                }
            }
            #pragma unroll
            for (int rr = 0; rr < CH; rr++) {
                int r = ch * CH + rr;
                hbuf0[j * PAD + r] = xla_tanh(__fadd_rn(ah[rr], blh));
                creg[r]            = xla_tanh(__fadd_rn(ac[rr], blc));
            }
        }
    }
    __syncthreads();   // also orders zsm reads before hbuf1 (alias) writes

    // loop-invariant b_hh for this unit's 4 gate columns (b_ih folded in E)
    float bhh0 = b_hh[j],       bhh1 = b_hh[256 + j];
    float bhh2 = b_hh[512 + j], bhh3 = b_hh[768 + j];

    float* hOld = hbuf0;
    float* hNew = hbuf1;
    // duplicated-packed W: element (k,j,half) at index (k*HID+j)*2 + half
    const ulonglong2* __restrict__ W2J =
        (const ulonglong2*)g_W2f + (size_t)j * 2;

    for (int s = 0; s < SEQN; s++) {
        // prefetch this step's gumbel early (data-independent)
        float gum = 0.0f;
        if (tid < TB * NUCV)
            gum = g_gum[(size_t)s * BATCH * NUCV +
                        (size_t)(rowBase + (tid >> 2)) * NUCV + (tid & 3)];

        // ---- gates: h @ W_hh via fma.rn.f32x2; W pre-duplicated, depth-1 LDG ----
        #pragma unroll
        for (int ch = 0; ch < TB / CH; ch++) {
            unsigned long long ai[CH/2], af_[CH/2], ag[CH/2], ao[CH/2];
            #pragma unroll
            for (int rp = 0; rp < CH/2; rp++) {
                ai[rp] = 0ULL; af_[rp] = 0ULL; ag[rp] = 0ULL; ao[rp] = 0ULL;
            }
            const float* hrow = hOld + ch * CH;
            ulonglong2 wA = W2J[0];                 // (wi,wi),(wf,wf)
            ulonglong2 wB = W2J[1];                 // (wg,wg),(wo,wo)
            #pragma unroll 4
            for (int k = 0; k < HID; k++) {
                // one-deep prefetch; k=256 row is zero-padded
                ulonglong2 nA = W2J[(size_t)(k + 1) * HID * 2];
                ulonglong2 nB = W2J[(size_t)(k + 1) * HID * 2 + 1];
                const ulonglong2* h4 = (const ulonglong2*)(hrow + k * PAD);
                #pragma unroll
                for (int q = 0; q < CH / 4; q++) {
                    ulonglong2 hp = h4[q];
                    ai [2*q]   = fma2(hp.x, wA.x, ai [2*q]);
                    af_[2*q]   = fma2(hp.x, wA.y, af_[2*q]);
                    ag [2*q]   = fma2(hp.x, wB.x, ag [2*q]);
                    ao [2*q]   = fma2(hp.x, wB.y, ao [2*q]);
                    ai [2*q+1] = fma2(hp.y, wA.x, ai [2*q+1]);
                    af_[2*q+1] = fma2(hp.y, wA.y, af_[2*q+1]);
                    ag [2*q+1] = fma2(hp.y, wB.x, ag [2*q+1]);
                    ao [2*q+1] = fma2(hp.y, wB.y, ao [2*q+1]);
                }
                wA = nA; wB = nB;
            }
            // ---- pointwise; association matches ((xW+b_ih)+hW)+b_hh ----
            #pragma unroll
            for (int rp = 0; rp < CH / 2; rp++) {
                float aiL, aiH, afL, afH, agL, agH, aoL, aoH;
                unpack2(ai [rp], aiL, aiH);
                unpack2(af_[rp], afL, afH);
                unpack2(ag [rp], agL, agH);
                unpack2(ao [rp], aoL, aoH);
                #pragma unroll
                for (int lane = 0; lane < 2; lane++) {
                    int r = ch * CH + 2 * rp + lane;
                    float aI = lane ? aiH : aiL;
                    float aF = lane ? afH : afL;
                    float aG = lane ? agH : agL;
                    float aO = lane ? aoH : aoL;
                    int tok = tokSm[r];
                    const float* Ev = Esm + tok * GATES + j;   // E already has +b_ih
                    float gi = __fadd_rn(__fadd_rn(Ev[0],   aI), bhh0);
                    float gf = __fadd_rn(__fadd_rn(Ev[256], aF), bhh1);
                    float gg = __fadd_rn(__fadd_rn(Ev[512], aG), bhh2);
                    float go = __fadd_rn(__fadd_rn(Ev[768], aO), bhh3);
                    float iv = xla_sigmoid(gi);
                    float fv = xla_sigmoid(gf);
                    float gv = xla_tanh(gg);
                    float ov = xla_sigmoid(go);
                    float cc = __fadd_rn(__fmul_rn(fv, creg[r]), __fmul_rn(iv, gv));
                    creg[r] = cc;
                    hNew[j * PAD + r] = __fmul_rn(ov, xla_tanh(cc));
                }
            }
        }
        __syncthreads();

        // ---- merged logits + categorical sampling with precomputed gumbel ----
        if (tid < TB * NUCV) {
            int r = tid >> 2, n = tid & 3;
            float acc = 0.0f;
            for (int k = 0; k < HID; k++)
                acc = __fmaf_rn(hNew[k * PAD + r], WoutSm[k * NUCV + n], acc);
            float lg = __fadd_rn(acc, boutSm[n]);
            size_t b = (size_t)(rowBase + r);
            out[(b * SEQN + s) * NUCV + n] = lg;

            float v = __fadd_rn(gum, lg);
            float bv = v; int bn = n;
            #pragma unroll
            for (int m = 1; m < 4; m <<= 1) {
                float ov = __shfl_xor_sync(0xffffffffu, bv, m);
                int   on = __shfl_xor_sync(0xffffffffu, bn, m);
                if (ov > bv || (ov == bv && on < bn)) { bv = ov; bn = on; }
            }
            if (n == 0) {
                tokSm[r] = bn;
                out[(size_t)BATCH * SEQN * NUCV + b * SEQN + s] = (float)bn;
            }
        }
        __syncthreads();

        float* t = hOld; hOld = hNew; hNew = t;
    }
}

extern "C" void kernel_launch(void* const* d_in, const int* in_sizes, int n_in,
                              void* d_out, int out_size) {
    (void)in_sizes; (void)n_in; (void)out_size;
    const float* z     = (const float*)d_in[0];
    const float* W_lh  = (const float*)d_in[1];
    const float* b_lh  = (const float*)d_in[2];
    const float* W_lc  = (const float*)d_in[3];
    const float* b_lc  = (const float*)d_in[4];
    const float* emb   = (const float*)d_in[5];
    const float* W_ih  = (const float*)d_in[6];
    const float* W_hh  = (const float*)d_in[7];
    const float* b_ih  = (const float*)d_in[8];
    const float* b_hh  = (const float*)d_in[9];
    const float* W_out = (const float*)d_in[10];
    const float* b_out = (const float*)d_in[11];
    float* out = (float*)d_out;

    // jax.random.split(key(42), 50), threefry_partitionable (foldlike)
    StepKeys keys;
    for (int s = 0; s < SEQN; s++) {
        unsigned o0, o1;
        tf2x32(0u, 42u, 0u, (unsigned)s, o0, o1);
        keys.k0[s] = o0;
        keys.k1[s] = o1;
    }

    ecomp_kernel<<<(VOCAB * GATES + 255) / 256, 256>>>(emb, W_ih, b_ih);
    wpack_kernel<<<((HID + 1) * HID + 255) / 256, 256>>>(W_hh);
    {
        size_t total = (size_t)SEQN * BATCH * NUCV;
        gumbel_kernel<<<(unsigned)((total + 255) / 256), 256>>>(keys);
    }

    cudaFuncSetAttribute(rnn_main, cudaFuncAttributeMaxDynamicSharedMemorySize, SMEM_BYTES);
    rnn_main<<<BATCH / TB, NTHREADS, SMEM_BYTES>>>(
        z, W_lh, b_lh, W_lc, b_lc, b_hh, W_out, b_out, out);
}

// round 16
// speedup vs baseline: 1.1457x; 1.1457x over previous
#include <cuda_runtime.h>
#include <cstdint>

#define BATCH   65536
#define LATENT  128
#define HID     256
#define GATES   1024
#define SEQN    50
#define NUCV    4
#define VOCAB   5
#define SOS_TOK 4

#define TB       32            // rows per CTA (single pass)
#define NTHREADS 256
#define PAD      36            // hT row stride: 144B = 16B-aligned

// SMEM layout (float offsets)
#define OFF_HA    0            // hbuf0 [256][36]
#define OFF_HB    9216         // hbuf1 [256][36]
#define OFF_ZS    9216         // zsm aliases hbuf1 (prologue-only)
#define OFF_CB    18432        // cbuf  [256][36] (cell state)
#define OFF_E     27648        // [5][1024] (b_ih folded)
#define OFF_WOUT  32768        // [256][4]
#define OFF_BOUT  33792        // [4]
#define OFF_TOK   33796        // [32]
#define SMEM_FLOATS 33828
#define SMEM_BYTES  (SMEM_FLOATS * 4)   // 135312 B -> 1 CTA/SM

struct StepKeys { unsigned int k0[SEQN]; unsigned int k1[SEQN]; };

__device__ float g_E[VOCAB * GATES];            // emb[v]@W_ih + b_ih (folded)
__device__ float4 g_Wp[(HID + 1) * HID];        // [k][j]=(wi,wf,wg,wo); +1 zero row
__device__ float g_gum[(size_t)SEQN * BATCH * NUCV];  // exact gumbel noise

// ---------------- packed f32x2 helpers (Blackwell sm_103a) ----------------
__device__ __forceinline__ unsigned long long pack2(float lo, float hi) {
    unsigned long long r;
    asm("mov.b64 %0, {%1, %2};" : "=l"(r) : "f"(lo), "f"(hi));
    return r;
}
__device__ __forceinline__ void unpack2(unsigned long long v, float& lo, float& hi) {
    asm("mov.b64 {%0, %1}, %2;" : "=f"(lo), "=f"(hi) : "l"(v));
}
// per-lane IEEE RN fused multiply-add on packed 2xf32 — bit-identical to
// two scalar __fmaf_rn per lane
__device__ __forceinline__ unsigned long long fma2(unsigned long long a,
                                                   unsigned long long b,
                                                   unsigned long long c) {
    unsigned long long d;
    asm("fma.rn.f32x2 %0, %1, %2, %3;" : "=l"(d) : "l"(a), "l"(b), "l"(c));
    return d;
}

// ---------------- Threefry-2x32 (matches jax/_src/prng.py) ----------------
__host__ __device__ __forceinline__ unsigned int rotl32(unsigned int x, int d) {
    return (x << d) | (x >> (32 - d));
}

__host__ __device__ __forceinline__ void tf2x32(unsigned int k0, unsigned int k1,
                                                unsigned int x0, unsigned int x1,
                                                unsigned int& o0, unsigned int& o1)
{
    unsigned int k2 = k0 ^ k1 ^ 0x1BD11BDAu;
    x0 += k0; x1 += k1;
    x0 += x1; x1 = rotl32(x1, 13); x1 ^= x0;
    x0 += x1; x1 = rotl32(x1, 15); x1 ^= x0;
    x0 += x1; x1 = rotl32(x1, 26); x1 ^= x0;
    x0 += x1; x1 = rotl32(x1, 6);  x1 ^= x0;
    x0 += k1; x1 += k2 + 1u;
    x0 += x1; x1 = rotl32(x1, 17); x1 ^= x0;
    x0 += x1; x1 = rotl32(x1, 29); x1 ^= x0;
    x0 += x1; x1 = rotl32(x1, 16); x1 ^= x0;
    x0 += x1; x1 = rotl32(x1, 24); x1 ^= x0;
    x0 += k2; x1 += k0 + 2u;
    x0 += x1; x1 = rotl32(x1, 13); x1 ^= x0;
    x0 += x1; x1 = rotl32(x1, 15); x1 ^= x0;
    x0 += x1; x1 = rotl32(x1, 26); x1 ^= x0;
    x0 += x1; x1 = rotl32(x1, 6);  x1 ^= x0;
    x0 += k0; x1 += k1 + 3u;
    x0 += x1; x1 = rotl32(x1, 17); x1 ^= x0;
    x0 += x1; x1 = rotl32(x1, 29); x1 ^= x0;
    x0 += x1; x1 = rotl32(x1, 16); x1 ^= x0;
    x0 += x1; x1 = rotl32(x1, 24); x1 ^= x0;
    x0 += k1; x1 += k2 + 4u;
    x0 += x1; x1 = rotl32(x1, 13); x1 ^= x0;
    x0 += x1; x1 = rotl32(x1, 15); x1 ^= x0;
    x0 += x1; x1 = rotl32(x1, 26); x1 ^= x0;
    x0 += x1; x1 = rotl32(x1, 6);  x1 ^= x0;
    x0 += k2; x1 += k0 + 5u;
    o0 = x0; o1 = x1;
}

// ---------------- XLA-exact activations ----------------
__device__ __forceinline__ float xla_tanh(float x) {
    float ax = fabsf(x);
    float xc = fminf(fmaxf(x, -7.90531110763549805f), 7.90531110763549805f);
    float x2 = __fmul_rn(xc, xc);
    float p = -2.76076847742355e-16f;
    p = __fadd_rn(__fmul_rn(p, x2), 2.00018790482477e-13f);
    p = __fadd_rn(__fmul_rn(p, x2), -8.60467152213735e-11f);
    p = __fadd_rn(__fmul_rn(p, x2), 5.12229709037114e-08f);
    p = __fadd_rn(__fmul_rn(p, x2), 1.48572235717979e-05f);
    p = __fadd_rn(__fmul_rn(p, x2), 6.37261928875436e-04f);
    p = __fadd_rn(__fmul_rn(p, x2), 4.89352455891786e-03f);
    float num = __fmul_rn(xc, p);
    float q = 1.19825839466702e-06f;
    q = __fadd_rn(__fmul_rn(q, x2), 1.18534705686654e-04f);
    q = __fadd_rn(__fmul_rn(q, x2), 2.26843463243900e-03f);
    q = __fadd_rn(__fmul_rn(q, x2), 4.89352518554385e-03f);
    float r = __fdiv_rn(num, q);
    return (ax < 0.0004f) ? x : r;
}

__device__ __forceinline__ float xla_sigmoid(float x) {
    return __fadd_rn(0.5f, __fmul_rn(0.5f, xla_tanh(__fmul_rn(0.5f, x))));
}

// correctly-rounded f32 log via double
__device__ __forceinline__ float exact_logf(float x) {
    return (float)log((double)x);
}

// ---------------- E-table kernel: E[v][col] = emb[v]@W_ih[:,col] + b_ih[col] ----
__global__ void ecomp_kernel(const float* __restrict__ emb,
                             const float* __restrict__ W_ih,
                             const float* __restrict__ b_ih) {
    int idx = blockIdx.x * blockDim.x + threadIdx.x;
    if (idx >= VOCAB * GATES) return;
    int v = idx / GATES, col = idx - v * GATES;
    float acc = 0.0f;
    for (int k = 0; k < HID; k++)
        acc = __fmaf_rn(emb[v * HID + k], W_ih[k * GATES + col], acc);
    g_E[idx] = __fadd_rn(acc, b_ih[col]);
}

// ---------------- W repack kernel: g_Wp[k][j] = (wi,wf,wg,wo) ----------------
__global__ void wpack_kernel(const float* __restrict__ W_hh) {
    int idx = blockIdx.x * blockDim.x + threadIdx.x;
    if (idx >= (HID + 1) * HID) return;
    int k = idx >> 8, j = idx & (HID - 1);
    float4 w;
    if (k < HID) {
        w.x = W_hh[(size_t)k * GATES + j];
        w.y = W_hh[(size_t)k * GATES + 256 + j];
        w.z = W_hh[(size_t)k * GATES + 512 + j];
        w.w = W_hh[(size_t)k * GATES + 768 + j];
    } else {
        w.x = w.y = w.z = w.w = 0.0f;   // prefetch overread row
    }
    g_Wp[idx] = w;
}

// ---------------- Gumbel precompute: exact, data-independent ----------------
__global__ void gumbel_kernel(StepKeys keys) {
    size_t idx = (size_t)blockIdx.x * blockDim.x + threadIdx.x;
    if (idx >= (size_t)SEQN * BATCH * NUCV) return;
    int s = (int)(idx / ((size_t)BATCH * NUCV));
    unsigned rem = (unsigned)(idx - (size_t)s * BATCH * NUCV);   // b*4+n
    unsigned o0, o1;
    tf2x32(keys.k0[s], keys.k1[s], 0u, rem, o0, o1);
    unsigned bits = o0 ^ o1;
    unsigned fb = (bits >> 9) | 0x3f800000u;
    float u = __fadd_rn(__uint_as_float(fb), -1.0f);
    u = fmaxf(u, 1.17549435e-38f);              // minval = tiny
    float lu  = exact_logf(u);
    g_gum[idx] = -exact_logf(-lu);
}

// ---------------- Main persistent-per-CTA LSTM kernel ----------------
__global__ void __launch_bounds__(NTHREADS, 1)
rnn_main(const float* __restrict__ z,
         const float* __restrict__ W_lh, const float* __restrict__ b_lh,
         const float* __restrict__ W_lc, const float* __restrict__ b_lc,
         const float* __restrict__ b_hh,
         const float* __restrict__ W_out, const float* __restrict__ b_out,
         float* __restrict__ out)
{
    extern __shared__ float sm[];
    float* hbuf0   = sm + OFF_HA;      // hT[unit][row], PAD-strided
    float* hbuf1   = sm + OFF_HB;
    float* zsm     = sm + OFF_ZS;      // aliases hbuf1 (prologue only)
    float* cbuf    = sm + OFF_CB;      // cell state, same layout as h
    float* Esm     = sm + OFF_E;       // [5][1024] (b_ih folded)
    float* WoutSm  = sm + OFF_WOUT;    // [256][4]
    float* boutSm  = sm + OFF_BOUT;    // [4]
    int*   tokSm   = (int*)(sm + OFF_TOK);  // [32]

    const int tid = threadIdx.x;
    const int j   = tid;                     // hidden unit owned by this thread
    const int rowBase = blockIdx.x * TB;

    // cooperative SMEM fills
    for (int i = tid; i < VOCAB * GATES; i += NTHREADS) Esm[i] = g_E[i];
    for (int i = tid; i < HID * NUCV; i += NTHREADS)    WoutSm[i] = W_out[i];
    if (tid < NUCV) boutSm[tid] = b_out[tid];
    if (tid < TB)   tokSm[tid]  = SOS_TOK;
    for (int i = tid; i < TB * LATENT; i += NTHREADS)
        zsm[i] = z[(size_t)rowBase * LATENT + i];
    __syncthreads();

    // ---- prologue: h0 = tanh(z@W_lh + b_lh), c0 = tanh(z@W_lc + b_lc) ----
    {
        const float* wlh = W_lh + j;
        const float* wlc = W_lc + j;
        float blh = b_lh[j], blc = b_lc[j];
        #pragma unroll
        for (int ch = 0; ch < 2; ch++) {
            float ah[16], ac[16];
            #pragma unroll
            for (int rr = 0; rr < 16; rr++) { ah[rr] = 0.0f; ac[rr] = 0.0f; }
            for (int k = 0; k < LATENT; k++) {
                float wh = wlh[k * HID];
                float wc = wlc[k * HID];
                #pragma unroll
                for (int rr = 0; rr < 16; rr++) {
                    float zv = zsm[(ch * 16 + rr) * LATENT + k];
                    ah[rr] = __fmaf_rn(zv, wh, ah[rr]);
                    ac[rr] = __fmaf_rn(zv, wc, ac[rr]);
                }
            }
            #pragma unroll
            for (int rr = 0; rr < 16; rr++) {
                int r = ch * 16 + rr;
                hbuf0[j * PAD + r] = xla_tanh(__fadd_rn(ah[rr], blh));
                cbuf [j * PAD + r] = xla_tanh(__fadd_rn(ac[rr], blc));
            }
        }
    }
    __syncthreads();   // also orders zsm reads before hbuf1 (alias) writes

    // loop-invariant b_hh for this unit's 4 gate columns (b_ih folded in E)
    float bhh0 = b_hh[j],       bhh1 = b_hh[256 + j];
    float bhh2 = b_hh[512 + j], bhh3 = b_hh[768 + j];

    float* hOld = hbuf0;
    float* hNew = hbuf1;
    const float4* __restrict__ WpJ = g_Wp + j;     // [k][j], stride HID per k

    for (int s = 0; s < SEQN; s++) {
        // prefetch this step's gumbel early (data-independent)
        float gum = 0.0f;
        if (tid < TB * NUCV)
            gum = g_gum[(size_t)s * BATCH * NUCV +
                        (size_t)(rowBase + (tid >> 2)) * NUCV + (tid & 3)];

        // ---- gates: full 32 rows in ONE pass — W read once per step ----
        unsigned long long ai[8], af_[8], ag[8], ao[8];   // row pairs 0..7
        unsigned long long ai2[8], af2[8], ag2[8], ao2[8]; // row pairs 8..15
        #pragma unroll
        for (int rp = 0; rp < 8; rp++) {
            ai[rp] = 0ULL; af_[rp] = 0ULL; ag[rp] = 0ULL; ao[rp] = 0ULL;
            ai2[rp] = 0ULL; af2[rp] = 0ULL; ag2[rp] = 0ULL; ao2[rp] = 0ULL;
        }
        {
            float4 wc = WpJ[0];
            #pragma unroll 1
            for (int k = 0; k < HID; k++) {
                float4 wn = WpJ[(k + 1) * HID];   // depth-1 prefetch (zero row pads)
                unsigned long long wi2 = pack2(wc.x, wc.x);
                unsigned long long wf2 = pack2(wc.y, wc.y);
                unsigned long long wg2 = pack2(wc.z, wc.z);
                unsigned long long wo2 = pack2(wc.w, wc.w);
                const ulonglong2* h4 = (const ulonglong2*)(hOld + k * PAD);
                #pragma unroll
                for (int q = 0; q < 4; q++) {      // rows 0..15
                    ulonglong2 hp = h4[q];
                    ai [2*q]   = fma2(hp.x, wi2, ai [2*q]);
                    af_[2*q]   = fma2(hp.x, wf2, af_[2*q]);
                    ag [2*q]   = fma2(hp.x, wg2, ag [2*q]);
                    ao [2*q]   = fma2(hp.x, wo2, ao [2*q]);
                    ai [2*q+1] = fma2(hp.y, wi2, ai [2*q+1]);
                    af_[2*q+1] = fma2(hp.y, wf2, af_[2*q+1]);
                    ag [2*q+1] = fma2(hp.y, wg2, ag [2*q+1]);
                    ao [2*q+1] = fma2(hp.y, wo2, ao [2*q+1]);
                }
                #pragma unroll
                for (int q = 0; q < 4; q++) {      // rows 16..31
                    ulonglong2 hp = h4[4 + q];
                    ai2[2*q]   = fma2(hp.x, wi2, ai2[2*q]);
                    af2[2*q]   = fma2(hp.x, wf2, af2[2*q]);
                    ag2[2*q]   = fma2(hp.x, wg2, ag2[2*q]);
                    ao2[2*q]   = fma2(hp.x, wo2, ao2[2*q]);
                    ai2[2*q+1] = fma2(hp.y, wi2, ai2[2*q+1]);
                    af2[2*q+1] = fma2(hp.y, wf2, af2[2*q+1]);
                    ag2[2*q+1] = fma2(hp.y, wg2, ag2[2*q+1]);
                    ao2[2*q+1] = fma2(hp.y, wo2, ao2[2*q+1]);
                }
                wc = wn;
            }
        }
        // ---- pointwise; association matches ((xW+b_ih)+hW)+b_hh ----
        #pragma unroll
        for (int half = 0; half < 2; half++) {
            #pragma unroll
            for (int rp = 0; rp < 8; rp++) {
                float aiL, aiH, afL, afH, agL, agH, aoL, aoH;
                if (half == 0) {
                    unpack2(ai [rp], aiL, aiH); unpack2(af_[rp], afL, afH);
                    unpack2(ag [rp], agL, agH); unpack2(ao [rp], aoL, aoH);
                } else {
                    unpack2(ai2[rp], aiL, aiH); unpack2(af2[rp], afL, afH);
                    unpack2(ag2[rp], agL, agH); unpack2(ao2[rp], aoL, aoH);
                }
                #pragma unroll
                for (int lane = 0; lane < 2; lane++) {
                    int r = half * 16 + 2 * rp + lane;
                    float aI = lane ? aiH : aiL;
                    float aF = lane ? afH : afL;
                    float aG = lane ? agH : agL;
                    float aO = lane ? aoH : aoL;
                    int tok = tokSm[r];
                    const float* Ev = Esm + tok * GATES + j;   // E has +b_ih
                    float gi = __fadd_rn(__fadd_rn(Ev[0],   aI), bhh0);
                    float gf = __fadd_rn(__fadd_rn(Ev[256], aF), bhh1);
                    float gg = __fadd_rn(__fadd_rn(Ev[512], aG), bhh2);
                    float go = __fadd_rn(__fadd_rn(Ev[768], aO), bhh3);
                    float iv = xla_sigmoid(gi);
                    float fv = xla_sigmoid(gf);
                    float gv = xla_tanh(gg);
                    float ov = xla_sigmoid(go);
                    float cold = cbuf[j * PAD + r];
                    float cc = __fadd_rn(__fmul_rn(fv, cold), __fmul_rn(iv, gv));
                    cbuf[j * PAD + r] = cc;
                    hNew[j * PAD + r] = __fmul_rn(ov, xla_tanh(cc));
                }
            }
        }
        __syncthreads();

        // ---- merged logits + categorical sampling with precomputed gumbel ----
        if (tid < TB * NUCV) {
            int r = tid >> 2, n = tid & 3;
            float acc = 0.0f;
            for (int k = 0; k < HID; k++)
                acc = __fmaf_rn(hNew[k * PAD + r], WoutSm[k * NUCV + n], acc);
            float lg = __fadd_rn(acc, boutSm[n]);
            size_t b = (size_t)(rowBase + r);
            out[(b * SEQN + s) * NUCV + n] = lg;

            float v = __fadd_rn(gum, lg);
            float bv = v; int bn = n;
            #pragma unroll
            for (int m = 1; m < 4; m <<= 1) {
                float ov = __shfl_xor_sync(0xffffffffu, bv, m);
                int   on = __shfl_xor_sync(0xffffffffu, bn, m);
                if (ov > bv || (ov == bv && on < bn)) { bv = ov; bn = on; }
            }
            if (n == 0) {
                tokSm[r] = bn;
                out[(size_t)BATCH * SEQN * NUCV + b * SEQN + s] = (float)bn;
            }
        }
        __syncthreads();

        float* t = hOld; hOld = hNew; hNew = t;
    }
}

extern "C" void kernel_launch(void* const* d_in, const int* in_sizes, int n_in,
                              void* d_out, int out_size) {
    (void)in_sizes; (void)n_in; (void)out_size;
    const float* z     = (const float*)d_in[0];
    const float* W_lh  = (const float*)d_in[1];
    const float* b_lh  = (const float*)d_in[2];
    const float* W_lc  = (const float*)d_in[3];
    const float* b_lc  = (const float*)d_in[4];
    const float* emb   = (const float*)d_in[5];
    const float* W_ih  = (const float*)d_in[6];
    const float* W_hh  = (const float*)d_in[7];
    const float* b_ih  = (const float*)d_in[8];
    const float* b_hh  = (const float*)d_in[9];
    const float* W_out = (const float*)d_in[10];
    const float* b_out = (const float*)d_in[11];
    float* out = (float*)d_out;

    // jax.random.split(key(42), 50), threefry_partitionable (foldlike)
    StepKeys keys;
    for (int s = 0; s < SEQN; s++) {
        unsigned o0, o1;
        tf2x32(0u, 42u, 0u, (unsigned)s, o0, o1);
        keys.k0[s] = o0;
        keys.k1[s] = o1;
    }

    ecomp_kernel<<<(VOCAB * GATES + 255) / 256, 256>>>(emb, W_ih, b_ih);
    wpack_kernel<<<((HID + 1) * HID + 255) / 256, 256>>>(W_hh);
    {
        size_t total = (size_t)SEQN * BATCH * NUCV;
        gumbel_kernel<<<(unsigned)((total + 255) / 256), 256>>>(keys);
    }

    cudaFuncSetAttribute(rnn_main, cudaFuncAttributeMaxDynamicSharedMemorySize, SMEM_BYTES);
    rnn_main<<<BATCH / TB, NTHREADS, SMEM_BYTES>>>(
        z, W_lh, b_lh, W_lc, b_lc, b_hh, W_out, b_out, out);
}

// round 17
// speedup vs baseline: 1.2182x; 1.0632x over previous
#include <cuda_runtime.h>
#include <cstdint>

#define BATCH   65536
#define LATENT  128
#define HID     256
#define GATES   1024
#define SEQN    50
#define NUCV    4
#define VOCAB   5
#define SOS_TOK 4

#define TB       32            // rows per CTA (single pass)
#define NTHREADS 256
#define PAD      36            // hT row stride: 144B = 16B-aligned

// SMEM layout (float offsets)
#define OFF_HA    0            // hbuf0 [256][36]
#define OFF_HB    9216         // hbuf1 [256][36]
#define OFF_ZS    9216         // zsm aliases hbuf1 (prologue-only)
#define OFF_CB    18432        // cbuf  [256][36] (cell state)
#define OFF_E     27648        // [5][1024] (b_ih folded)
#define OFF_WOUT  32768        // [256][4]
#define OFF_BOUT  33792        // [4]
#define OFF_TOK   33796        // [32]
#define SMEM_FLOATS 33828
#define SMEM_BYTES  (SMEM_FLOATS * 4)   // 135312 B -> 1 CTA/SM

struct StepKeys { unsigned int k0[SEQN]; unsigned int k1[SEQN]; };

__device__ float g_E[VOCAB * GATES];            // emb[v]@W_ih + b_ih (folded)
__device__ float4 g_Wp[(HID + 2) * HID];        // [k][j]=(wi,wf,wg,wo); +2 zero rows
__device__ float g_gum[(size_t)SEQN * BATCH * NUCV];  // exact gumbel noise

// ---------------- packed f32x2 helpers (Blackwell sm_103a) ----------------
__device__ __forceinline__ unsigned long long pack2(float lo, float hi) {
    unsigned long long r;
    asm("mov.b64 %0, {%1, %2};" : "=l"(r) : "f"(lo), "f"(hi));
    return r;
}
__device__ __forceinline__ void unpack2(unsigned long long v, float& lo, float& hi) {
    asm("mov.b64 {%0, %1}, %2;" : "=f"(lo), "=f"(hi) : "l"(v));
}
// per-lane IEEE RN fused multiply-add on packed 2xf32 — bit-identical to
// two scalar __fmaf_rn per lane
__device__ __forceinline__ unsigned long long fma2(unsigned long long a,
                                                   unsigned long long b,
                                                   unsigned long long c) {
    unsigned long long d;
    asm("fma.rn.f32x2 %0, %1, %2, %3;" : "=l"(d) : "l"(a), "l"(b), "l"(c));
    return d;
}

// ---------------- Threefry-2x32 (matches jax/_src/prng.py) ----------------
__host__ __device__ __forceinline__ unsigned int rotl32(unsigned int x, int d) {
    return (x << d) | (x >> (32 - d));
}

__host__ __device__ __forceinline__ void tf2x32(unsigned int k0, unsigned int k1,
                                                unsigned int x0, unsigned int x1,
                                                unsigned int& o0, unsigned int& o1)
{
    unsigned int k2 = k0 ^ k1 ^ 0x1BD11BDAu;
    x0 += k0; x1 += k1;
    x0 += x1; x1 = rotl32(x1, 13); x1 ^= x0;
    x0 += x1; x1 = rotl32(x1, 15); x1 ^= x0;
    x0 += x1; x1 = rotl32(x1, 26); x1 ^= x0;
    x0 += x1; x1 = rotl32(x1, 6);  x1 ^= x0;
    x0 += k1; x1 += k2 + 1u;
    x0 += x1; x1 = rotl32(x1, 17); x1 ^= x0;
    x0 += x1; x1 = rotl32(x1, 29); x1 ^= x0;
    x0 += x1; x1 = rotl32(x1, 16); x1 ^= x0;
    x0 += x1; x1 = rotl32(x1, 24); x1 ^= x0;
    x0 += k2; x1 += k0 + 2u;
    x0 += x1; x1 = rotl32(x1, 13); x1 ^= x0;
    x0 += x1; x1 = rotl32(x1, 15); x1 ^= x0;
    x0 += x1; x1 = rotl32(x1, 26); x1 ^= x0;
    x0 += x1; x1 = rotl32(x1, 6);  x1 ^= x0;
    x0 += k0; x1 += k1 + 3u;
    x0 += x1; x1 = rotl32(x1, 17); x1 ^= x0;
    x0 += x1; x1 = rotl32(x1, 29); x1 ^= x0;
    x0 += x1; x1 = rotl32(x1, 16); x1 ^= x0;
    x0 += x1; x1 = rotl32(x1, 24); x1 ^= x0;
    x0 += k1; x1 += k2 + 4u;
    x0 += x1; x1 = rotl32(x1, 13); x1 ^= x0;
    x0 += x1; x1 = rotl32(x1, 15); x1 ^= x0;
    x0 += x1; x1 = rotl32(x1, 26); x1 ^= x0;
    x0 += x1; x1 = rotl32(x1, 6);  x1 ^= x0;
    x0 += k2; x1 += k0 + 5u;
    o0 = x0; o1 = x1;
}

// ---------------- XLA-exact activations ----------------
__device__ __forceinline__ float xla_tanh(float x) {
    float ax = fabsf(x);
    float xc = fminf(fmaxf(x, -7.90531110763549805f), 7.90531110763549805f);
    float x2 = __fmul_rn(xc, xc);
    float p = -2.76076847742355e-16f;
    p = __fadd_rn(__fmul_rn(p, x2), 2.00018790482477e-13f);
    p = __fadd_rn(__fmul_rn(p, x2), -8.60467152213735e-11f);
    p = __fadd_rn(__fmul_rn(p, x2), 5.12229709037114e-08f);
    p = __fadd_rn(__fmul_rn(p, x2), 1.48572235717979e-05f);
    p = __fadd_rn(__fmul_rn(p, x2), 6.37261928875436e-04f);
    p = __fadd_rn(__fmul_rn(p, x2), 4.89352455891786e-03f);
    float num = __fmul_rn(xc, p);
    float q = 1.19825839466702e-06f;
    q = __fadd_rn(__fmul_rn(q, x2), 1.18534705686654e-04f);
    q = __fadd_rn(__fmul_rn(q, x2), 2.26843463243900e-03f);
    q = __fadd_rn(__fmul_rn(q, x2), 4.89352518554385e-03f);
    float r = __fdiv_rn(num, q);
    return (ax < 0.0004f) ? x : r;
}

__device__ __forceinline__ float xla_sigmoid(float x) {
    return __fadd_rn(0.5f, __fmul_rn(0.5f, xla_tanh(__fmul_rn(0.5f, x))));
}

// correctly-rounded f32 log via double
__device__ __forceinline__ float exact_logf(float x) {
    return (float)log((double)x);
}

// ---------------- E-table kernel: E[v][col] = emb[v]@W_ih[:,col] + b_ih[col] ----
__global__ void ecomp_kernel(const float* __restrict__ emb,
                             const float* __restrict__ W_ih,
                             const float* __restrict__ b_ih) {
    int idx = blockIdx.x * blockDim.x + threadIdx.x;
    if (idx >= VOCAB * GATES) return;
    int v = idx / GATES, col = idx - v * GATES;
    float acc = 0.0f;
    for (int k = 0; k < HID; k++)
        acc = __fmaf_rn(emb[v * HID + k], W_ih[k * GATES + col], acc);
    g_E[idx] = __fadd_rn(acc, b_ih[col]);
}

// ---------------- W repack kernel: g_Wp[k][j] = (wi,wf,wg,wo) ----------------
__global__ void wpack_kernel(const float* __restrict__ W_hh) {
    int idx = blockIdx.x * blockDim.x + threadIdx.x;
    if (idx >= (HID + 2) * HID) return;
    int k = idx >> 8, j = idx & (HID - 1);
    float4 w;
    if (k < HID) {
        w.x = W_hh[(size_t)k * GATES + j];
        w.y = W_hh[(size_t)k * GATES + 256 + j];
        w.z = W_hh[(size_t)k * GATES + 512 + j];
        w.w = W_hh[(size_t)k * GATES + 768 + j];
    } else {
        w.x = w.y = w.z = w.w = 0.0f;   // prefetch overread rows
    }
    g_Wp[idx] = w;
}

// ---------------- Gumbel precompute: exact, data-independent ----------------
__global__ void gumbel_kernel(StepKeys keys) {
    size_t idx = (size_t)blockIdx.x * blockDim.x + threadIdx.x;
    if (idx >= (size_t)SEQN * BATCH * NUCV) return;
    int s = (int)(idx / ((size_t)BATCH * NUCV));
    unsigned rem = (unsigned)(idx - (size_t)s * BATCH * NUCV);   // b*4+n
    unsigned o0, o1;
    tf2x32(keys.k0[s], keys.k1[s], 0u, rem, o0, o1);
    unsigned bits = o0 ^ o1;
    unsigned fb = (bits >> 9) | 0x3f800000u;
    float u = __fadd_rn(__uint_as_float(fb), -1.0f);
    u = fmaxf(u, 1.17549435e-38f);              // minval = tiny
    float lu  = exact_logf(u);
    g_gum[idx] = -exact_logf(-lu);
}

// ---------------- Main persistent-per-CTA LSTM kernel ----------------
__global__ void __launch_bounds__(NTHREADS, 1)
rnn_main(const float* __restrict__ z,
         const float* __restrict__ W_lh, const float* __restrict__ b_lh,
         const float* __restrict__ W_lc, const float* __restrict__ b_lc,
         const float* __restrict__ b_hh,
         const float* __restrict__ W_out, const float* __restrict__ b_out,
         float* __restrict__ out)
{
    extern __shared__ float sm[];
    float* hbuf0   = sm + OFF_HA;      // hT[unit][row], PAD-strided
    float* hbuf1   = sm + OFF_HB;
    float* zsm     = sm + OFF_ZS;      // aliases hbuf1 (prologue only)
    float* cbuf    = sm + OFF_CB;      // cell state, same layout as h
    float* Esm     = sm + OFF_E;       // [5][1024] (b_ih folded)
    float* WoutSm  = sm + OFF_WOUT;    // [256][4]
    float* boutSm  = sm + OFF_BOUT;    // [4]
    int*   tokSm   = (int*)(sm + OFF_TOK);  // [32]

    const int tid = threadIdx.x;
    const int j   = tid;                     // hidden unit owned by this thread
    const int rowBase = blockIdx.x * TB;

    // cooperative SMEM fills
    for (int i = tid; i < VOCAB * GATES; i += NTHREADS) Esm[i] = g_E[i];
    for (int i = tid; i < HID * NUCV; i += NTHREADS)    WoutSm[i] = W_out[i];
    if (tid < NUCV) boutSm[tid] = b_out[tid];
    if (tid < TB)   tokSm[tid]  = SOS_TOK;
    for (int i = tid; i < TB * LATENT; i += NTHREADS)
        zsm[i] = z[(size_t)rowBase * LATENT + i];
    __syncthreads();

    // ---- prologue: h0 = tanh(z@W_lh + b_lh), c0 = tanh(z@W_lc + b_lc) ----
    {
        const float* wlh = W_lh + j;
        const float* wlc = W_lc + j;
        float blh = b_lh[j], blc = b_lc[j];
        #pragma unroll
        for (int ch = 0; ch < 2; ch++) {
            float ah[16], ac[16];
            #pragma unroll
            for (int rr = 0; rr < 16; rr++) { ah[rr] = 0.0f; ac[rr] = 0.0f; }
            for (int k = 0; k < LATENT; k++) {
                float wh = wlh[k * HID];
                float wc = wlc[k * HID];
                #pragma unroll
                for (int rr = 0; rr < 16; rr++) {
                    float zv = zsm[(ch * 16 + rr) * LATENT + k];
                    ah[rr] = __fmaf_rn(zv, wh, ah[rr]);
                    ac[rr] = __fmaf_rn(zv, wc, ac[rr]);
                }
            }
            #pragma unroll
            for (int rr = 0; rr < 16; rr++) {
                int r = ch * 16 + rr;
                hbuf0[j * PAD + r] = xla_tanh(__fadd_rn(ah[rr], blh));
                cbuf [j * PAD + r] = xla_tanh(__fadd_rn(ac[rr], blc));
            }
        }
    }
    __syncthreads();   // also orders zsm reads before hbuf1 (alias) writes

    // loop-invariant b_hh for this unit's 4 gate columns (b_ih folded in E)
    float bhh0 = b_hh[j],       bhh1 = b_hh[256 + j];
    float bhh2 = b_hh[512 + j], bhh3 = b_hh[768 + j];

    float* hOld = hbuf0;
    float* hNew = hbuf1;
    const float4* __restrict__ WpJ = g_Wp + j;     // [k][j], stride HID per k

    for (int s = 0; s < SEQN; s++) {
        // prefetch this step's gumbel early (data-independent)
        float gum = 0.0f;
        if (tid < TB * NUCV)
            gum = g_gum[(size_t)s * BATCH * NUCV +
                        (size_t)(rowBase + (tid >> 2)) * NUCV + (tid & 3)];

        // ---- gates: full 32 rows in ONE pass — W read once per step ----
        unsigned long long ai[8], af_[8], ag[8], ao[8];    // row pairs 0..7
        unsigned long long ai2[8], af2[8], ag2[8], ao2[8]; // row pairs 8..15
        #pragma unroll
        for (int rp = 0; rp < 8; rp++) {
            ai[rp] = 0ULL; af_[rp] = 0ULL; ag[rp] = 0ULL; ao[rp] = 0ULL;
            ai2[rp] = 0ULL; af2[rp] = 0ULL; ag2[rp] = 0ULL; ao2[rp] = 0ULL;
        }
        {
            float4 wc = WpJ[0];
            #pragma unroll 2
            for (int k = 0; k < HID; k++) {
                // depth-1 W prefetch (zero rows pad the overread)
                float4 wn = WpJ[(k + 1) * HID];
                unsigned long long wi2 = pack2(wc.x, wc.x);
                unsigned long long wf2 = pack2(wc.y, wc.y);
                unsigned long long wg2 = pack2(wc.z, wc.z);
                unsigned long long wo2 = pack2(wc.w, wc.w);
                // front-batch all 8 h vectors (32 rows) — unroll 2 lets ptxas
                // hoist k+1's LDS into k's FMA body
                const ulonglong2* h4 = (const ulonglong2*)(hOld + k * PAD);
                ulonglong2 hp[8];
                #pragma unroll
                for (int q = 0; q < 8; q++) hp[q] = h4[q];
                #pragma unroll
                for (int q = 0; q < 4; q++) {      // rows 0..15
                    ai [2*q]   = fma2(hp[q].x, wi2, ai [2*q]);
                    af_[2*q]   = fma2(hp[q].x, wf2, af_[2*q]);
                    ag [2*q]   = fma2(hp[q].x, wg2, ag [2*q]);
                    ao [2*q]   = fma2(hp[q].x, wo2, ao [2*q]);
                    ai [2*q+1] = fma2(hp[q].y, wi2, ai [2*q+1]);
                    af_[2*q+1] = fma2(hp[q].y, wf2, af_[2*q+1]);
                    ag [2*q+1] = fma2(hp[q].y, wg2, ag [2*q+1]);
                    ao [2*q+1] = fma2(hp[q].y, wo2, ao [2*q+1]);
                }
                #pragma unroll
                for (int q = 0; q < 4; q++) {      // rows 16..31
                    ai2[2*q]   = fma2(hp[4+q].x, wi2, ai2[2*q]);
                    af2[2*q]   = fma2(hp[4+q].x, wf2, af2[2*q]);
                    ag2[2*q]   = fma2(hp[4+q].x, wg2, ag2[2*q]);
                    ao2[2*q]   = fma2(hp[4+q].x, wo2, ao2[2*q]);
                    ai2[2*q+1] = fma2(hp[4+q].y, wi2, ai2[2*q+1]);
                    af2[2*q+1] = fma2(hp[4+q].y, wf2, af2[2*q+1]);
                    ag2[2*q+1] = fma2(hp[4+q].y, wg2, ag2[2*q+1]);
                    ao2[2*q+1] = fma2(hp[4+q].y, wo2, ao2[2*q+1]);
                }
                wc = wn;
            }
        }
        // ---- pointwise; association matches ((xW+b_ih)+hW)+b_hh ----
        #pragma unroll
        for (int half = 0; half < 2; half++) {
            #pragma unroll
            for (int rp = 0; rp < 8; rp++) {
                float aiL, aiH, afL, afH, agL, agH, aoL, aoH;
                if (half == 0) {
                    unpack2(ai [rp], aiL, aiH); unpack2(af_[rp], afL, afH);
                    unpack2(ag [rp], agL, agH); unpack2(ao [rp], aoL, aoH);
                } else {
                    unpack2(ai2[rp], aiL, aiH); unpack2(af2[rp], afL, afH);
                    unpack2(ag2[rp], agL, agH); unpack2(ao2[rp], aoL, aoH);
                }
                #pragma unroll
                for (int lane = 0; lane < 2; lane++) {
                    int r = half * 16 + 2 * rp + lane;
                    float aI = lane ? aiH : aiL;
                    float aF = lane ? afH : afL;
                    float aG = lane ? agH : agL;
                    float aO = lane ? aoH : aoL;
                    int tok = tokSm[r];
                    const float* Ev = Esm + tok * GATES + j;   // E has +b_ih
                    float gi = __fadd_rn(__fadd_rn(Ev[0],   aI), bhh0);
                    float gf = __fadd_rn(__fadd_rn(Ev[256], aF), bhh1);
                    float gg = __fadd_rn(__fadd_rn(Ev[512], aG), bhh2);
                    float go = __fadd_rn(__fadd_rn(Ev[768], aO), bhh3);
                    float iv = xla_sigmoid(gi);
                    float fv = xla_sigmoid(gf);
                    float gv = xla_tanh(gg);
                    float ov = xla_sigmoid(go);
                    float cold = cbuf[j * PAD + r];
                    float cc = __fadd_rn(__fmul_rn(fv, cold), __fmul_rn(iv, gv));
                    cbuf[j * PAD + r] = cc;
                    hNew[j * PAD + r] = __fmul_rn(ov, xla_tanh(cc));
                }
            }
        }
        __syncthreads();

        // ---- merged logits + categorical sampling with precomputed gumbel ----
        if (tid < TB * NUCV) {
            int r = tid >> 2, n = tid & 3;
            float acc = 0.0f;
            for (int k = 0; k < HID; k++)
                acc = __fmaf_rn(hNew[k * PAD + r], WoutSm[k * NUCV + n], acc);
            float lg = __fadd_rn(acc, boutSm[n]);
            size_t b = (size_t)(rowBase + r);
            out[(b * SEQN + s) * NUCV + n] = lg;

            float v = __fadd_rn(gum, lg);
            float bv = v; int bn = n;
            #pragma unroll
            for (int m = 1; m < 4; m <<= 1) {
                float ov = __shfl_xor_sync(0xffffffffu, bv, m);
                int   on = __shfl_xor_sync(0xffffffffu, bn, m);
                if (ov > bv || (ov == bv && on < bn)) { bv = ov; bn = on; }
            }
            if (n == 0) {
                tokSm[r] = bn;
                out[(size_t)BATCH * SEQN * NUCV + b * SEQN + s] = (float)bn;
            }
        }
        __syncthreads();

        float* t = hOld; hOld = hNew; hNew = t;
    }
}

extern "C" void kernel_launch(void* const* d_in, const int* in_sizes, int n_in,
                              void* d_out, int out_size) {
    (void)in_sizes; (void)n_in; (void)out_size;
    const float* z     = (const float*)d_in[0];
    const float* W_lh  = (const float*)d_in[1];
    const float* b_lh  = (const float*)d_in[2];
    const float* W_lc  = (const float*)d_in[3];
    const float* b_lc  = (const float*)d_in[4];
    const float* emb   = (const float*)d_in[5];
    const float* W_ih  = (const float*)d_in[6];
    const float* W_hh  = (const float*)d_in[7];
    const float* b_ih  = (const float*)d_in[8];
    const float* b_hh  = (const float*)d_in[9];
    const float* W_out = (const float*)d_in[10];
    const float* b_out = (const float*)d_in[11];
    float* out = (float*)d_out;

    // jax.random.split(key(42), 50), threefry_partitionable (foldlike)
    StepKeys keys;
    for (int s = 0; s < SEQN; s++) {
        unsigned o0, o1;
        tf2x32(0u, 42u, 0u, (unsigned)s, o0, o1);
        keys.k0[s] = o0;
        keys.k1[s] = o1;
    }

    ecomp_kernel<<<(VOCAB * GATES + 255) / 256, 256>>>(emb, W_ih, b_ih);
    wpack_kernel<<<((HID + 2) * HID + 255) / 256, 256>>>(W_hh);
    {
        size_t total = (size_t)SEQN * BATCH * NUCV;
        gumbel_kernel<<<(unsigned)((total + 255) / 256), 256>>>(keys);
    }

    cudaFuncSetAttribute(rnn_main, cudaFuncAttributeMaxDynamicSharedMemorySize, SMEM_BYTES);
    rnn_main<<<BATCH / TB, NTHREADS, SMEM_BYTES>>>(
        z, W_lh, b_lh, W_lc, b_lc, b_hh, W_out, b_out, out);
}